// round 12
// baseline (speedup 1.0000x reference)
#include <cuda_runtime.h>
#include <cstdint>
#include <math.h>

#define B_ 2
#define S_ 2048
#define E_ 1024
#define H_ 16
#define D_ 64
#define M_ (B_*S_)

#define NEGINF (-1e30f)

// Scratch (allocation-free rule: __device__ globals)
__device__ float g_Q[B_*S_*E_];
__device__ float g_K[B_*S_*E_];
__device__ float g_V[B_*S_*E_];
__device__ float g_Vt[B_*H_*D_*S_];   // V transposed: [(b*H+h)][d][s]
__device__ float g_C[B_*S_*E_];

// ===========================================================================
// mma.sync + cp.async helpers (family-portable sm_80+; tcgen05 unavailable:
// harness targets virtual arch compute_100, forbidding accelerated-family PTX)
// ===========================================================================
__device__ __forceinline__ uint32_t smem_u32(const void* p) {
    uint32_t a;
    asm("{ .reg .u64 t; cvta.to.shared.u64 t, %1; cvt.u32.u64 %0, t; }"
        : "=r"(a) : "l"(p));
    return a;
}
__device__ __forceinline__ uint32_t tf32_bits(float a) {
    uint32_t u;
    asm("cvt.rna.tf32.f32 %0, %1;" : "=r"(u) : "f"(a));
    return u;
}
// pack two floats as bf16x2: e0 -> low half, e1 -> high half (PTX: 1st src = hi)
__device__ __forceinline__ uint32_t pack_bf16(float e0, float e1) {
    uint32_t r;
    asm("cvt.rn.bf16x2.f32 %0, %1, %2;" : "=r"(r) : "f"(e1), "f"(e0));
    return r;
}
__device__ __forceinline__ void ldsm4(uint32_t& r0, uint32_t& r1,
                                      uint32_t& r2, uint32_t& r3, uint32_t addr) {
    asm volatile("ldmatrix.sync.aligned.m8n8.x4.shared.b16 {%0,%1,%2,%3}, [%4];"
                 : "=r"(r0), "=r"(r1), "=r"(r2), "=r"(r3) : "r"(addr));
}
__device__ __forceinline__ void mma_tf32(float* c, const uint32_t* a,
                                         uint32_t b0, uint32_t b1) {
    asm volatile("mma.sync.aligned.m16n8k8.row.col.f32.tf32.tf32.f32 "
                 "{%0,%1,%2,%3}, {%4,%5,%6,%7}, {%8,%9}, {%0,%1,%2,%3};"
                 : "+f"(c[0]), "+f"(c[1]), "+f"(c[2]), "+f"(c[3])
                 : "r"(a[0]), "r"(a[1]), "r"(a[2]), "r"(a[3]), "r"(b0), "r"(b1));
}
__device__ __forceinline__ void mma_bf16(float* c, const uint32_t* a,
                                         uint32_t b0, uint32_t b1) {
    asm volatile("mma.sync.aligned.m16n8k16.row.col.f32.bf16.bf16.f32 "
                 "{%0,%1,%2,%3}, {%4,%5,%6,%7}, {%8,%9}, {%0,%1,%2,%3};"
                 : "+f"(c[0]), "+f"(c[1]), "+f"(c[2]), "+f"(c[3])
                 : "r"(a[0]), "r"(a[1]), "r"(a[2]), "r"(a[3]), "r"(b0), "r"(b1));
}
__device__ __forceinline__ void split4(const uint32_t* r, uint32_t* hi, uint32_t* lo) {
    #pragma unroll
    for (int i = 0; i < 4; i++) {
        const float v = __uint_as_float(r[i]);
        hi[i] = tf32_bits(v);
        lo[i] = tf32_bits(v - __uint_as_float(hi[i]));
    }
}
__device__ __forceinline__ void cvt4(const uint32_t* r, uint32_t* hi) {
    #pragma unroll
    for (int i = 0; i < 4; i++) hi[i] = tf32_bits(__uint_as_float(r[i]));
}
__device__ __forceinline__ void cpasync16(uint32_t dst, const void* src) {
    asm volatile("cp.async.cg.shared.global [%0], [%1], 16;" :: "r"(dst), "l"(src));
}
__device__ __forceinline__ void cpasync_commit() {
    asm volatile("cp.async.commit_group;");
}
template<int N> __device__ __forceinline__ void cpasync_wait() {
    asm volatile("cp.async.wait_group %0;" :: "n"(N));
}

// ===========================================================================
// bf16 2-split mma.sync GEMM (NT): C[128x128] = A[M,1024] * Bw[N,1024]^T
// v2: 512 threads / 16 warps (4m x 4n, warp tile 32x32) for issue-latency
// hiding (was 8 warps @ issue=24.5%). Same 80-byte-row conflict-free
// layout, split-once-at-STS, ping-pong stages, ONE barrier per K-tile.
// ===========================================================================
#define ROWB 80                         // 32 bf16 = 64B + 16B pad
#define TILE_BF (128 * ROWB)            // 10240 B per (hi|lo)x(A|B) tile
#define GSTAGE_B (4 * TILE_BF)          // Ahi|Alo|Bhi|Blo = 40960 B
#define GEMM_SMEM (2 * GSTAGE_B + 128)
#define GT 512                          // threads per GEMM block

__device__ __forceinline__ void tc_gemm_body(const float* __restrict__ A,
                                             const float* __restrict__ Bw,
                                             float* __restrict__ C,
                                             int bm, int bn)
{
    extern __shared__ char smraw[];
    char* smb = (char*)(((uintptr_t)smraw + 127) & ~(uintptr_t)127);
    const uint32_t sbase = smem_u32(smb);

    const int tid  = threadIdx.x;
    const int wid  = tid >> 5;
    const int lane = tid & 31;
    const int wm = (wid >> 2) * 32;      // 0,32,64,96
    const int wn = (wid & 3) * 32;       // 0,32,64,96

    const int rlbA   = (lane & 7) + ((lane >> 3) & 1) * 8;
    const int col16A = (lane >> 4) & 1;
    const int rlbB   = (lane & 7) + ((lane >> 4) & 1) * 8;
    const int col16B = (lane >> 3) & 1;

    // fragment base offsets (80B rows, conflict-free, no swizzle)
    uint32_t aOff[2], bOff[2];
    #pragma unroll
    for (int f = 0; f < 2; f++) aOff[f] = (wm + f * 16 + rlbA) * ROWB + col16A * 16;
    #pragma unroll
    for (int p = 0; p < 2; p++) bOff[p] = (wn + p * 16 + rlbB) * ROWB + col16B * 16;

    const float* Abase = A  + (size_t)bm * E_;
    const float* Bbase = Bw + (size_t)bn * E_;

    float acc[2][4][4] = {};
    float4 rgA[2], rgB[2];

    // preload k-tile 0 (1024 float4 per operand / 512 threads = 2 each)
    #pragma unroll
    for (int l = 0; l < 2; l++) {
        const int idx = tid + l * GT;
        const int row = idx >> 3, c4 = idx & 7;
        rgA[l] = *(const float4*)(Abase + (size_t)row * E_ + c4 * 4);
        rgB[l] = *(const float4*)(Bbase + (size_t)row * E_ + c4 * 4);
    }

    for (int kt = 0; kt < 32; kt++) {
        const uint32_t cur = (kt & 1) * GSTAGE_B;
        char* st = smb + cur;

        // ---- split to bf16 hi/lo and STS (once per element) ----
        #pragma unroll
        for (int l = 0; l < 2; l++) {
            const int idx = tid + l * GT;
            const int row = idx >> 3, c4 = idx & 7;
            const int off = row * ROWB + c4 * 8;
            {
                float4 a = rgA[l];
                uint32_t h0 = pack_bf16(a.x, a.y);
                uint32_t h1 = pack_bf16(a.z, a.w);
                float f0 = __uint_as_float(h0 << 16);
                float f1 = __uint_as_float(h0 & 0xffff0000u);
                float f2 = __uint_as_float(h1 << 16);
                float f3 = __uint_as_float(h1 & 0xffff0000u);
                uint32_t l0 = pack_bf16(a.x - f0, a.y - f1);
                uint32_t l1 = pack_bf16(a.z - f2, a.w - f3);
                *(uint2*)(st + off)           = make_uint2(h0, h1);
                *(uint2*)(st + TILE_BF + off) = make_uint2(l0, l1);
            }
            {
                float4 b = rgB[l];
                uint32_t h0 = pack_bf16(b.x, b.y);
                uint32_t h1 = pack_bf16(b.z, b.w);
                float f0 = __uint_as_float(h0 << 16);
                float f1 = __uint_as_float(h0 & 0xffff0000u);
                float f2 = __uint_as_float(h1 << 16);
                float f3 = __uint_as_float(h1 & 0xffff0000u);
                uint32_t l0 = pack_bf16(b.x - f0, b.y - f1);
                uint32_t l1 = pack_bf16(b.z - f2, b.w - f3);
                *(uint2*)(st + 2 * TILE_BF + off) = make_uint2(h0, h1);
                *(uint2*)(st + 3 * TILE_BF + off) = make_uint2(l0, l1);
            }
        }
        __syncthreads();

        // prefetch next k-tile into registers
        if (kt + 1 < 32) {
            const int k0 = (kt + 1) * 32;
            #pragma unroll
            for (int l = 0; l < 2; l++) {
                const int idx = tid + l * GT;
                const int row = idx >> 3, c4 = idx & 7;
                rgA[l] = *(const float4*)(Abase + (size_t)row * E_ + k0 + c4 * 4);
                rgB[l] = *(const float4*)(Bbase + (size_t)row * E_ + k0 + c4 * 4);
            }
        }

        const uint32_t sA = sbase + cur;

        // ---- compute: 2 k16 slices, 3 bf16 streams, 32x32 warp tile ----
        #pragma unroll
        for (int s = 0; s < 2; s++) {
            const uint32_t kb = s * 32;
            uint32_t ah[2][4], al[2][4];
            #pragma unroll
            for (int f = 0; f < 2; f++) {
                ldsm4(ah[f][0], ah[f][1], ah[f][2], ah[f][3],
                      sA + aOff[f] + kb);
                ldsm4(al[f][0], al[f][1], al[f][2], al[f][3],
                      sA + TILE_BF + aOff[f] + kb);
            }
            #pragma unroll
            for (int p = 0; p < 2; p++) {
                uint32_t bh[4], bl[4];
                ldsm4(bh[0], bh[1], bh[2], bh[3],
                      sA + 2 * TILE_BF + bOff[p] + kb);
                ldsm4(bl[0], bl[1], bl[2], bl[3],
                      sA + 3 * TILE_BF + bOff[p] + kb);
                #pragma unroll
                for (int gg = 0; gg < 2; gg++) {
                    const int g = p * 2 + gg;
                    const uint32_t b0h = bh[gg * 2], b1h = bh[gg * 2 + 1];
                    const uint32_t b0l = bl[gg * 2], b1l = bl[gg * 2 + 1];
                    #pragma unroll
                    for (int f = 0; f < 2; f++) {
                        mma_bf16(acc[f][g], ah[f], b0h, b1h);
                        mma_bf16(acc[f][g], ah[f], b0l, b1l);
                        mma_bf16(acc[f][g], al[f], b0h, b1h);
                    }
                }
            }
        }
    }

    #pragma unroll
    for (int f = 0; f < 2; f++) {
        const int r0 = bm + wm + f * 16 + (lane >> 2);
        #pragma unroll
        for (int g = 0; g < 4; g++) {
            const int cc = bn + wn + g * 8 + (lane & 3) * 2;
            *(float2*)(C + (size_t)r0 * E_ + cc) =
                make_float2(acc[f][g][0], acc[f][g][1]);
            *(float2*)(C + (size_t)(r0 + 8) * E_ + cc) =
                make_float2(acc[f][g][2], acc[f][g][3]);
        }
    }
}

__global__ __launch_bounds__(GT)
void tc_gemm_qkv(const float* __restrict__ x, const float* __restrict__ Wq,
                 const float* __restrict__ Wk, const float* __restrict__ Wv)
{
    const int sel = blockIdx.x >> 3;
    const float* Bw = (sel == 0) ? Wq : (sel == 1) ? Wk : Wv;
    float* C = (sel == 0) ? g_Q : (sel == 1) ? g_K : g_V;
    tc_gemm_body(x, Bw, C, blockIdx.y * 128, (blockIdx.x & 7) * 128);
}

__global__ __launch_bounds__(GT)
void tc_gemm_o(const float* __restrict__ Wo, float* __restrict__ out)
{
    tc_gemm_body(g_C, Wo, out, blockIdx.y * 128, blockIdx.x * 128);
}

// ===========================================================================
// V transpose: g_V [b][s][h*64+d] -> g_Vt [(b*H+h)][d][s]  (unchanged)
// ===========================================================================
__global__ __launch_bounds__(256)
void v_transpose()
{
    __shared__ float ts[64 * 65];
    const int st = blockIdx.x;
    const int h = blockIdx.y, b = blockIdx.z;
    const float* Vg = g_V + (size_t)b * S_ * E_ + h * D_;
    float* Vt = g_Vt + (size_t)(b * H_ + h) * D_ * S_;
    const int tid = threadIdx.x;

    #pragma unroll
    for (int l = 0; l < 4; l++) {
        const int idx = tid + l * 256;
        const int s = idx >> 4, c4 = idx & 15;
        float4 v = *(const float4*)(Vg + (size_t)(st * 64 + s) * E_ + c4 * 4);
        ts[(c4 * 4 + 0) * 65 + s] = v.x;
        ts[(c4 * 4 + 1) * 65 + s] = v.y;
        ts[(c4 * 4 + 2) * 65 + s] = v.z;
        ts[(c4 * 4 + 3) * 65 + s] = v.w;
    }
    __syncthreads();
    #pragma unroll
    for (int l = 0; l < 4; l++) {
        const int idx = tid + l * 256;
        const int d = idx >> 4, c4 = idx & 15;
        float4 w = make_float4(ts[d * 65 + c4 * 4 + 0], ts[d * 65 + c4 * 4 + 1],
                               ts[d * 65 + c4 * 4 + 2], ts[d * 65 + c4 * 4 + 3]);
        *(float4*)(Vt + (size_t)d * S_ + st * 64 + c4 * 4) = w;
    }
}

// ===========================================================================
// Flash attention, mma.sync (UNCHANGED from round 11 — passed @ 2.155e-4):
// cp.async 2-stage K/V ring; tf32 3-stream QK, single-stream PV.
// (bf16 QK was evaluated and REJECTED: 2^-16 score error x8 scale ~ 1e-3.)
// ===========================================================================
#define FST_STAGE 32768                 // per-stage: K raw 16KB + V raw 16KB
#define FST_TOTAL (2 * FST_STAGE + 128)

__device__ __forceinline__ void flash_issue_kv(uint32_t sdst,
                                               const float* __restrict__ Kg,
                                               const float* __restrict__ Vtg,
                                               int jt, int tid)
{
    #pragma unroll
    for (int l = 0; l < 4; l++) {
        const int idx = tid + l * 256;
        const int row = idx >> 4, c4 = idx & 15;
        const int off = (c4 >> 3) * 8192 + row * 128 +
                        (((c4 & 7) * 16) ^ ((row & 7) << 4));
        cpasync16(sdst + off,         Kg + (size_t)(jt * 64 + row) * E_ + c4 * 4);
        cpasync16(sdst + 16384 + off, Vtg + (size_t)row * S_ + jt * 64 + c4 * 4);
    }
    cpasync_commit();
}

__global__ __launch_bounds__(256)
void flash_mma()
{
    extern __shared__ char fraw[];
    char* fsm = (char*)(((uintptr_t)fraw + 127) & ~(uintptr_t)127);
    const uint32_t sb = smem_u32(fsm);

    const int tid = threadIdx.x, wid = tid >> 5, lane = tid & 31;
    const int qt = (S_ / 128 - 1) - (int)blockIdx.x;   // heavy tiles first
    const int h = blockIdx.y, b = blockIdx.z;

    const float* Qg  = g_Q + (size_t)b * S_ * E_ + h * D_;
    const float* Kg  = g_K + (size_t)b * S_ * E_ + h * D_;
    const float* Vtg = g_Vt + (size_t)(b * H_ + h) * D_ * S_;
    float* Og = g_C + (size_t)b * S_ * E_ + h * D_;

    const int rlbA = (lane & 7) + ((lane >> 3) & 1) * 8;
    const int c16A = (lane >> 4) & 1;
    const int rlbB = (lane & 7) + ((lane >> 4) & 1) * 8;
    const int c16B = (lane >> 3) & 1;
    const uint32_t aX = ((rlbA & 7) << 4) ^ (c16A * 16);
    const uint32_t bX = ((rlbB & 7) << 4) ^ (c16B * 16);
    const int wq = wid * 16;
    const uint32_t rA = wq + rlbA;
    uint32_t bR[4];
    #pragma unroll
    for (int p = 0; p < 4; p++) bR[p] = (p * 16 + rlbB) * 128;

    const int qq   = lane & 3;
    const int srcA = (lane & ~3) | (qq >> 1);
    const int srcB = srcA + 2;
    const int selo = qq & 1;

    // prologue: KV tile 0 in flight; stage Q raw through stage-1 buffer
    flash_issue_kv(sb, Kg, Vtg, 0, tid);
    #pragma unroll
    for (int l = 0; l < 8; l++) {
        const int idx = tid + l * 256;
        const int row = idx >> 4, c4 = idx & 15;
        float4 q = *(const float4*)(Qg + (size_t)(qt * 128 + row) * E_ + c4 * 4);
        const int off = FST_STAGE + (c4 >> 3) * 16384 + row * 128 +
                        (((c4 & 7) * 16) ^ ((row & 7) << 4));
        *(float4*)(fsm + off) = q;
    }
    __syncthreads();
    uint32_t qr[8][4];
    #pragma unroll
    for (int s = 0; s < 8; s++) {
        const uint32_t ad = FST_STAGE + (s >> 2) * 16384 + rA * 128 +
                            (((s & 3) * 32) ^ aX);
        ldsm4(qr[s][0], qr[s][1], qr[s][2], qr[s][3], sb + ad);
    }
    __syncthreads();

    float o[8][4] = {};
    float mrow[2] = {NEGINF, NEGINF};
    float lrow[2] = {0.0f, 0.0f};

    const int nj = 2 * qt + 2;
    for (int jt = 0; jt < nj; jt++) {
        cpasync_wait<0>();
        __syncthreads();

        if (jt + 1 < nj)
            flash_issue_kv(sb + ((jt + 1) & 1) * FST_STAGE, Kg, Vtg, jt + 1, tid);

        const uint32_t cur = (jt & 1) * FST_STAGE;

        float sc[8][4] = {};
        #pragma unroll
        for (int s = 0; s < 8; s++) {
            const uint32_t cof = cur + (s >> 2) * 8192;
            const uint32_t colb = (s & 3) * 32;
            uint32_t qh[4], ql[4];
            split4(qr[s], qh, ql);
            uint32_t kh[4][4], kl[4][4];
            #pragma unroll
            for (int p = 0; p < 4; p++) {
                uint32_t kr[4];
                ldsm4(kr[0], kr[1], kr[2], kr[3], sb + cof + bR[p] + (colb ^ bX));
                split4(kr, kh[p], kl[p]);
            }
            #pragma unroll
            for (int nt = 0; nt < 8; nt++) {
                const uint32_t b0h = kh[nt >> 1][(nt & 1) * 2];
                const uint32_t b1h = kh[nt >> 1][(nt & 1) * 2 + 1];
                const uint32_t b0l = kl[nt >> 1][(nt & 1) * 2];
                const uint32_t b1l = kl[nt >> 1][(nt & 1) * 2 + 1];
                mma_tf32(sc[nt], qh, b0h, b1h);
                mma_tf32(sc[nt], qh, b0l, b1l);
                mma_tf32(sc[nt], ql, b0h, b1h);
            }
        }

        const bool maskt = (jt >= 2 * qt);
        const int qr1 = qt * 128 + wq + (lane >> 2);
        const int kcb = jt * 64 + 2 * (lane & 3);
        #pragma unroll
        for (int ri = 0; ri < 2; ri++) {
            const int qrow = qr1 + ri * 8;
            float mx = NEGINF;
            #pragma unroll
            for (int nt = 0; nt < 8; nt++) {
                float s0 = sc[nt][2 * ri] * 8.0f;
                float s1 = sc[nt][2 * ri + 1] * 8.0f;
                if (maskt) {
                    const int c = kcb + nt * 8;
                    if (c > qrow)     s0 = NEGINF;
                    if (c + 1 > qrow) s1 = NEGINF;
                }
                sc[nt][2 * ri]     = s0;
                sc[nt][2 * ri + 1] = s1;
                mx = fmaxf(mx, fmaxf(s0, s1));
            }
            mx = fmaxf(mx, __shfl_xor_sync(0xffffffffu, mx, 1));
            mx = fmaxf(mx, __shfl_xor_sync(0xffffffffu, mx, 2));
            const float mnew = fmaxf(mrow[ri], mx);
            const float alpha = __expf(mrow[ri] - mnew);
            float sum = 0.0f;
            #pragma unroll
            for (int nt = 0; nt < 8; nt++) {
                const float p0 = __expf(sc[nt][2 * ri] - mnew);
                const float p1 = __expf(sc[nt][2 * ri + 1] - mnew);
                sc[nt][2 * ri] = p0; sc[nt][2 * ri + 1] = p1;
                sum += p0 + p1;
                o[nt][2 * ri]     *= alpha;
                o[nt][2 * ri + 1] *= alpha;
            }
            sum += __shfl_xor_sync(0xffffffffu, sum, 1);
            sum += __shfl_xor_sync(0xffffffffu, sum, 2);
            lrow[ri] = lrow[ri] * alpha + sum;
            mrow[ri] = mnew;
        }

        #pragma unroll
        for (int kk = 0; kk < 8; kk++) {
            float v00 = __shfl_sync(0xffffffffu, sc[kk][0], srcA);
            float v01 = __shfl_sync(0xffffffffu, sc[kk][1], srcA);
            float v10 = __shfl_sync(0xffffffffu, sc[kk][0], srcB);
            float v11 = __shfl_sync(0xffffffffu, sc[kk][1], srcB);
            float w00 = __shfl_sync(0xffffffffu, sc[kk][2], srcA);
            float w01 = __shfl_sync(0xffffffffu, sc[kk][3], srcA);
            float w10 = __shfl_sync(0xffffffffu, sc[kk][2], srcB);
            float w11 = __shfl_sync(0xffffffffu, sc[kk][3], srcB);
            uint32_t ph[4];
            ph[0] = tf32_bits(selo ? v01 : v00);
            ph[1] = tf32_bits(selo ? w01 : w00);
            ph[2] = tf32_bits(selo ? v11 : v10);
            ph[3] = tf32_bits(selo ? w11 : w10);

            const uint32_t cof = cur + 16384 + (kk >> 2) * 8192;
            const uint32_t colb = (kk & 3) * 32;
            uint32_t vh[4][4];
            #pragma unroll
            for (int p = 0; p < 4; p++) {
                uint32_t vr[4];
                ldsm4(vr[0], vr[1], vr[2], vr[3], sb + cof + bR[p] + (colb ^ bX));
                cvt4(vr, vh[p]);
            }
            #pragma unroll
            for (int nt = 0; nt < 8; nt++)
                mma_tf32(o[nt], ph, vh[nt >> 1][(nt & 1) * 2],
                                    vh[nt >> 1][(nt & 1) * 2 + 1]);
        }
    }

    const float inv0 = 1.0f / lrow[0];
    const float inv1 = 1.0f / lrow[1];
    const int gr1 = qt * 128 + wq + (lane >> 2);
    #pragma unroll
    for (int nt = 0; nt < 8; nt++) {
        const int col = nt * 8 + 2 * (lane & 3);
        *(float2*)(Og + (size_t)gr1 * E_ + col) =
            make_float2(o[nt][0] * inv0, o[nt][1] * inv0);
        *(float2*)(Og + (size_t)(gr1 + 8) * E_ + col) =
            make_float2(o[nt][2] * inv1, o[nt][3] * inv1);
    }
}

// ===========================================================================
extern "C" void kernel_launch(void* const* d_in, const int* in_sizes, int n_in,
                              void* d_out, int out_size)
{
    const float* x  = (const float*)d_in[0];
    const float* Wq = (const float*)d_in[1];
    const float* Wk = (const float*)d_in[2];
    const float* Wv = (const float*)d_in[3];
    const float* Wo = (const float*)d_in[4];
    float* out = (float*)d_out;

    cudaFuncSetAttribute(tc_gemm_qkv, cudaFuncAttributeMaxDynamicSharedMemorySize, GEMM_SMEM);
    cudaFuncSetAttribute(tc_gemm_o,   cudaFuncAttributeMaxDynamicSharedMemorySize, GEMM_SMEM);
    cudaFuncSetAttribute(flash_mma,   cudaFuncAttributeMaxDynamicSharedMemorySize, FST_TOTAL);

    dim3 gq(24, 32);
    tc_gemm_qkv<<<gq, GT, GEMM_SMEM>>>(x, Wq, Wk, Wv);

    dim3 gt(32, 16, 2);
    v_transpose<<<gt, 256>>>();

    dim3 ga(S_ / 128, H_, B_);
    flash_mma<<<ga, 256, FST_TOTAL>>>();

    dim3 go(8, 32);
    tc_gemm_o<<<go, GT, GEMM_SMEM>>>(Wo, out);
}

// round 13
// speedup vs baseline: 1.1610x; 1.1610x over previous
#include <cuda_runtime.h>
#include <cstdint>
#include <math.h>

#define B_ 2
#define S_ 2048
#define E_ 1024
#define H_ 16
#define D_ 64
#define M_ (B_*S_)

#define NEGINF (-1e30f)

// Scratch (allocation-free rule: __device__ globals)
__device__ float g_Q[B_*S_*E_];
__device__ float g_K[B_*S_*E_];
__device__ float g_V[B_*S_*E_];
__device__ float g_Vt[B_*H_*D_*S_];   // V transposed: [(b*H+h)][d][s]
__device__ float g_C[B_*S_*E_];

// ===========================================================================
// mma.sync + cp.async helpers (family-portable sm_80+; tcgen05 unavailable:
// harness targets virtual arch compute_100, forbidding accelerated-family PTX)
// ===========================================================================
__device__ __forceinline__ uint32_t smem_u32(const void* p) {
    uint32_t a;
    asm("{ .reg .u64 t; cvta.to.shared.u64 t, %1; cvt.u32.u64 %0, t; }"
        : "=r"(a) : "l"(p));
    return a;
}
__device__ __forceinline__ uint32_t tf32_bits(float a) {
    uint32_t u;
    asm("cvt.rna.tf32.f32 %0, %1;" : "=r"(u) : "f"(a));
    return u;
}
// pack two floats as bf16x2: e0 -> low half, e1 -> high half (PTX: 1st src = hi)
__device__ __forceinline__ uint32_t pack_bf16(float e0, float e1) {
    uint32_t r;
    asm("cvt.rn.bf16x2.f32 %0, %1, %2;" : "=r"(r) : "f"(e1), "f"(e0));
    return r;
}
__device__ __forceinline__ void ldsm4(uint32_t& r0, uint32_t& r1,
                                      uint32_t& r2, uint32_t& r3, uint32_t addr) {
    asm volatile("ldmatrix.sync.aligned.m8n8.x4.shared.b16 {%0,%1,%2,%3}, [%4];"
                 : "=r"(r0), "=r"(r1), "=r"(r2), "=r"(r3) : "r"(addr));
}
__device__ __forceinline__ void mma_tf32(float* c, const uint32_t* a,
                                         uint32_t b0, uint32_t b1) {
    asm volatile("mma.sync.aligned.m16n8k8.row.col.f32.tf32.tf32.f32 "
                 "{%0,%1,%2,%3}, {%4,%5,%6,%7}, {%8,%9}, {%0,%1,%2,%3};"
                 : "+f"(c[0]), "+f"(c[1]), "+f"(c[2]), "+f"(c[3])
                 : "r"(a[0]), "r"(a[1]), "r"(a[2]), "r"(a[3]), "r"(b0), "r"(b1));
}
__device__ __forceinline__ void mma_bf16(float* c, const uint32_t* a,
                                         uint32_t b0, uint32_t b1) {
    asm volatile("mma.sync.aligned.m16n8k16.row.col.f32.bf16.bf16.f32 "
                 "{%0,%1,%2,%3}, {%4,%5,%6,%7}, {%8,%9}, {%0,%1,%2,%3};"
                 : "+f"(c[0]), "+f"(c[1]), "+f"(c[2]), "+f"(c[3])
                 : "r"(a[0]), "r"(a[1]), "r"(a[2]), "r"(a[3]), "r"(b0), "r"(b1));
}
__device__ __forceinline__ void cvt4(const uint32_t* r, uint32_t* hi) {
    #pragma unroll
    for (int i = 0; i < 4; i++) hi[i] = tf32_bits(__uint_as_float(r[i]));
}
__device__ __forceinline__ void cpasync16(uint32_t dst, const void* src) {
    asm volatile("cp.async.cg.shared.global [%0], [%1], 16;" :: "r"(dst), "l"(src));
}
__device__ __forceinline__ void cpasync_commit() {
    asm volatile("cp.async.commit_group;");
}
template<int N> __device__ __forceinline__ void cpasync_wait() {
    asm volatile("cp.async.wait_group %0;" :: "n"(N));
}
// float4 -> packed bf16 hi (uint2) + lo (uint2)
__device__ __forceinline__ void bf16_split_f4(float4 a, uint2& hi, uint2& lo) {
    uint32_t h0 = pack_bf16(a.x, a.y);
    uint32_t h1 = pack_bf16(a.z, a.w);
    float f0 = __uint_as_float(h0 << 16);
    float f1 = __uint_as_float(h0 & 0xffff0000u);
    float f2 = __uint_as_float(h1 << 16);
    float f3 = __uint_as_float(h1 & 0xffff0000u);
    hi = make_uint2(h0, h1);
    lo = make_uint2(pack_bf16(a.x - f0, a.y - f1), pack_bf16(a.z - f2, a.w - f3));
}

// ===========================================================================
// bf16 2-split mma.sync GEMM (NT) — ROUND-11 CONFIG (8 warps; best measured).
// 80-byte rows (conflict-free), split-once-at-STS, ping-pong, 1 barrier/K-tile.
// ===========================================================================
#define ROWB 80                         // 32 bf16 = 64B + 16B pad
#define TILE_BF (128 * ROWB)            // 10240 B per (hi|lo)x(A|B) tile
#define GSTAGE_B (4 * TILE_BF)          // Ahi|Alo|Bhi|Blo = 40960 B
#define GEMM_SMEM (2 * GSTAGE_B + 128)

__device__ __forceinline__ void tc_gemm_body(const float* __restrict__ A,
                                             const float* __restrict__ Bw,
                                             float* __restrict__ C,
                                             int bm, int bn)
{
    extern __shared__ char smraw[];
    char* smb = (char*)(((uintptr_t)smraw + 127) & ~(uintptr_t)127);
    const uint32_t sbase = smem_u32(smb);

    const int tid  = threadIdx.x;
    const int wid  = tid >> 5;
    const int lane = tid & 31;
    const int wm = (wid >> 2) * 64;
    const int wn = (wid & 3) * 32;

    const int rlbA   = (lane & 7) + ((lane >> 3) & 1) * 8;
    const int col16A = (lane >> 4) & 1;
    const int rlbB   = (lane & 7) + ((lane >> 4) & 1) * 8;
    const int col16B = (lane >> 3) & 1;

    uint32_t aOff[4], bOff[2];
    #pragma unroll
    for (int f = 0; f < 4; f++) aOff[f] = (wm + f * 16 + rlbA) * ROWB + col16A * 16;
    #pragma unroll
    for (int p = 0; p < 2; p++) bOff[p] = (wn + p * 16 + rlbB) * ROWB + col16B * 16;

    const float* Abase = A  + (size_t)bm * E_;
    const float* Bbase = Bw + (size_t)bn * E_;

    float acc[4][4][4] = {};
    float4 rgA[4], rgB[4];

    #pragma unroll
    for (int l = 0; l < 4; l++) {
        const int idx = tid + l * 256;
        const int row = idx >> 3, c4 = idx & 7;
        rgA[l] = *(const float4*)(Abase + (size_t)row * E_ + c4 * 4);
        rgB[l] = *(const float4*)(Bbase + (size_t)row * E_ + c4 * 4);
    }

    for (int kt = 0; kt < 32; kt++) {
        const uint32_t cur = (kt & 1) * GSTAGE_B;
        char* st = smb + cur;

        #pragma unroll
        for (int l = 0; l < 4; l++) {
            const int idx = tid + l * 256;
            const int row = idx >> 3, c4 = idx & 7;
            const int off = row * ROWB + c4 * 8;
            uint2 hi, lo;
            bf16_split_f4(rgA[l], hi, lo);
            *(uint2*)(st + off)           = hi;
            *(uint2*)(st + TILE_BF + off) = lo;
            bf16_split_f4(rgB[l], hi, lo);
            *(uint2*)(st + 2 * TILE_BF + off) = hi;
            *(uint2*)(st + 3 * TILE_BF + off) = lo;
        }
        __syncthreads();

        if (kt + 1 < 32) {
            const int k0 = (kt + 1) * 32;
            #pragma unroll
            for (int l = 0; l < 4; l++) {
                const int idx = tid + l * 256;
                const int row = idx >> 3, c4 = idx & 7;
                rgA[l] = *(const float4*)(Abase + (size_t)row * E_ + k0 + c4 * 4);
                rgB[l] = *(const float4*)(Bbase + (size_t)row * E_ + k0 + c4 * 4);
            }
        }

        const uint32_t sA = sbase + cur;

        #pragma unroll
        for (int s = 0; s < 2; s++) {
            const uint32_t kb = s * 32;
            uint32_t ah[4][4], al[4][4];
            #pragma unroll
            for (int f = 0; f < 4; f++) {
                ldsm4(ah[f][0], ah[f][1], ah[f][2], ah[f][3], sA + aOff[f] + kb);
                ldsm4(al[f][0], al[f][1], al[f][2], al[f][3],
                      sA + TILE_BF + aOff[f] + kb);
            }
            #pragma unroll
            for (int p = 0; p < 2; p++) {
                uint32_t bh[4], bl[4];
                ldsm4(bh[0], bh[1], bh[2], bh[3], sA + 2 * TILE_BF + bOff[p] + kb);
                ldsm4(bl[0], bl[1], bl[2], bl[3], sA + 3 * TILE_BF + bOff[p] + kb);
                #pragma unroll
                for (int gg = 0; gg < 2; gg++) {
                    const int g = p * 2 + gg;
                    const uint32_t b0h = bh[gg * 2], b1h = bh[gg * 2 + 1];
                    const uint32_t b0l = bl[gg * 2], b1l = bl[gg * 2 + 1];
                    #pragma unroll
                    for (int f = 0; f < 4; f++) {
                        mma_bf16(acc[f][g], ah[f], b0h, b1h);
                        mma_bf16(acc[f][g], ah[f], b0l, b1l);
                        mma_bf16(acc[f][g], al[f], b0h, b1h);
                    }
                }
            }
        }
    }

    #pragma unroll
    for (int f = 0; f < 4; f++) {
        const int r0 = bm + wm + f * 16 + (lane >> 2);
        #pragma unroll
        for (int g = 0; g < 4; g++) {
            const int cc = bn + wn + g * 8 + (lane & 3) * 2;
            *(float2*)(C + (size_t)r0 * E_ + cc) =
                make_float2(acc[f][g][0], acc[f][g][1]);
            *(float2*)(C + (size_t)(r0 + 8) * E_ + cc) =
                make_float2(acc[f][g][2], acc[f][g][3]);
        }
    }
}

__global__ __launch_bounds__(256)
void tc_gemm_qkv(const float* __restrict__ x, const float* __restrict__ Wq,
                 const float* __restrict__ Wk, const float* __restrict__ Wv)
{
    const int sel = blockIdx.x >> 3;
    const float* Bw = (sel == 0) ? Wq : (sel == 1) ? Wk : Wv;
    float* C = (sel == 0) ? g_Q : (sel == 1) ? g_K : g_V;
    tc_gemm_body(x, Bw, C, blockIdx.y * 128, (blockIdx.x & 7) * 128);
}

__global__ __launch_bounds__(256)
void tc_gemm_o(const float* __restrict__ Wo, float* __restrict__ out)
{
    tc_gemm_body(g_C, Wo, out, blockIdx.y * 128, blockIdx.x * 128);
}

// ===========================================================================
// V transpose: g_V [b][s][h*64+d] -> g_Vt [(b*H+h)][d][s]  (unchanged)
// ===========================================================================
__global__ __launch_bounds__(256)
void v_transpose()
{
    __shared__ float ts[64 * 65];
    const int st = blockIdx.x;
    const int h = blockIdx.y, b = blockIdx.z;
    const float* Vg = g_V + (size_t)b * S_ * E_ + h * D_;
    float* Vt = g_Vt + (size_t)(b * H_ + h) * D_ * S_;
    const int tid = threadIdx.x;

    #pragma unroll
    for (int l = 0; l < 4; l++) {
        const int idx = tid + l * 256;
        const int s = idx >> 4, c4 = idx & 15;
        float4 v = *(const float4*)(Vg + (size_t)(st * 64 + s) * E_ + c4 * 4);
        ts[(c4 * 4 + 0) * 65 + s] = v.x;
        ts[(c4 * 4 + 1) * 65 + s] = v.y;
        ts[(c4 * 4 + 2) * 65 + s] = v.z;
        ts[(c4 * 4 + 3) * 65 + s] = v.w;
    }
    __syncthreads();
    #pragma unroll
    for (int l = 0; l < 4; l++) {
        const int idx = tid + l * 256;
        const int d = idx >> 4, c4 = idx & 15;
        float4 w = make_float4(ts[d * 65 + c4 * 4 + 0], ts[d * 65 + c4 * 4 + 1],
                               ts[d * 65 + c4 * 4 + 2], ts[d * 65 + c4 * 4 + 3]);
        *(float4*)(Vt + (size_t)d * S_ + st * 64 + c4 * 4) = w;
    }
}

// ===========================================================================
// Flash attention v6:
//  - QK on bf16 2-split m16n8k16 (halves QK MMA instructions vs tf32 3-stream)
//    K pre-split to packed bf16 at STS (LDG+reg prefetch, GEMM-proven path);
//    144-byte rows => ldmatrix conflict-free without swizzle.
//  - Q split once to bf16 fragments at prologue (registers).
//  - PV unchanged: raw-f32 V via cp.async 2-stage ring, tf32 single-stream.
//  - one barrier per KV tile.
// ===========================================================================
#define KROW 144                        // 64 bf16 = 128B + 16B pad
#define KHALF (64 * KROW)               // 9216 B (one K hi or lo tile)
#define VOF (2 * KHALF)                 // 18432: V raw f32 (16384 B)
#define FSTG (VOF + 16384)              // 34816 B per stage
#define QST (2 * FSTG)                  // Q staging: Qhi | Qlo (18432 each)
#define QHALF (128 * KROW)              // 18432
#define FST_TOTAL (QST + 2 * QHALF + 128)

__device__ __forceinline__ void flash_issue_v(uint32_t stage_base,
                                              const float* __restrict__ Vtg,
                                              int jt, int tid)
{
    #pragma unroll
    for (int l = 0; l < 4; l++) {
        const int idx = tid + l * 256;
        const int row = idx >> 4, c4 = idx & 15;
        const int off = (c4 >> 3) * 8192 + row * 128 +
                        (((c4 & 7) * 16) ^ ((row & 7) << 4));
        cpasync16(stage_base + VOF + off, Vtg + (size_t)row * S_ + jt * 64 + c4 * 4);
    }
    cpasync_commit();
}

__global__ __launch_bounds__(256)
void flash_mma()
{
    extern __shared__ char fraw[];
    char* fsm = (char*)(((uintptr_t)fraw + 127) & ~(uintptr_t)127);
    const uint32_t sb = smem_u32(fsm);

    const int tid = threadIdx.x, wid = tid >> 5, lane = tid & 31;
    const int qt = (S_ / 128 - 1) - (int)blockIdx.x;   // heavy tiles first
    const int h = blockIdx.y, b = blockIdx.z;

    const float* Qg  = g_Q + (size_t)b * S_ * E_ + h * D_;
    const float* Kg  = g_K + (size_t)b * S_ * E_ + h * D_;
    const float* Vtg = g_Vt + (size_t)(b * H_ + h) * D_ * S_;
    float* Og = g_C + (size_t)b * S_ * E_ + h * D_;

    const int rlbA = (lane & 7) + ((lane >> 3) & 1) * 8;
    const int c16A = (lane >> 4) & 1;
    const int rlbB = (lane & 7) + ((lane >> 4) & 1) * 8;
    const int c16B = (lane >> 3) & 1;
    const int wq = wid * 16;

    // bf16 Q/K fragment bases (144B rows, no swizzle)
    const uint32_t aQ = (wq + rlbA) * KROW + c16A * 16;
    uint32_t bK[4];
    #pragma unroll
    for (int p = 0; p < 4; p++) bK[p] = (p * 16 + rlbB) * KROW + c16B * 16;

    // tf32 V fragment bases (128B swizzled rows) — unchanged from v5
    const uint32_t bX = ((rlbB & 7) << 4) ^ (c16B * 16);
    uint32_t bR[4];
    #pragma unroll
    for (int p = 0; p < 4; p++) bR[p] = (p * 16 + rlbB) * 128;

    // quad-shuffle constants for C->A relayout (PV)
    const int qq   = lane & 3;
    const int srcA = (lane & ~3) | (qq >> 1);
    const int srcB = srcA + 2;
    const int selo = qq & 1;

    // ---- prologue: K0 LDG, V0 cp.async, Q stage+split+extract ----
    float4 rgK[4];
    #pragma unroll
    for (int l = 0; l < 4; l++) {
        const int idx = tid + l * 256;
        const int row = idx >> 4, c4 = idx & 15;
        rgK[l] = *(const float4*)(Kg + (size_t)row * E_ + c4 * 4);
    }
    flash_issue_v(sb, Vtg, 0, tid);

    #pragma unroll
    for (int l = 0; l < 8; l++) {
        const int idx = tid + l * 256;
        const int row = idx >> 4, c4 = idx & 15;
        float4 q = *(const float4*)(Qg + (size_t)(qt * 128 + row) * E_ + c4 * 4);
        const int off = QST + row * KROW + c4 * 8;
        uint2 hi, lo;
        bf16_split_f4(q, hi, lo);
        *(uint2*)(fsm + off)         = hi;
        *(uint2*)(fsm + QHALF + off) = lo;
    }
    __syncthreads();
    uint32_t qh[4][4], ql[4][4];
    #pragma unroll
    for (int s = 0; s < 4; s++) {
        const uint32_t ad = QST + aQ + s * 32;
        ldsm4(qh[s][0], qh[s][1], qh[s][2], qh[s][3], sb + ad);
        ldsm4(ql[s][0], ql[s][1], ql[s][2], ql[s][3], sb + QHALF + ad);
    }

    float o[8][4] = {};
    float mrow[2] = {NEGINF, NEGINF};
    float lrow[2] = {0.0f, 0.0f};

    const int nj = 2 * qt + 2;
    for (int jt = 0; jt < nj; jt++) {
        const uint32_t cur = (jt & 1) * FSTG;
        char* st = fsm + cur;

        // ---- STS K_jt (bf16 hi/lo split) ----
        #pragma unroll
        for (int l = 0; l < 4; l++) {
            const int idx = tid + l * 256;
            const int row = idx >> 4, c4 = idx & 15;
            const int off = row * KROW + c4 * 8;
            uint2 hi, lo;
            bf16_split_f4(rgK[l], hi, lo);
            *(uint2*)(st + off)         = hi;
            *(uint2*)(st + KHALF + off) = lo;
        }
        cpasync_wait<0>();          // V_jt arrived (this thread)
        __syncthreads();            // K_jt + V_jt visible; jt-1 compute done

        // ---- prefetch next tile: K via LDG, V via cp.async ----
        if (jt + 1 < nj) {
            const int jn = jt + 1;
            #pragma unroll
            for (int l = 0; l < 4; l++) {
                const int idx = tid + l * 256;
                const int row = idx >> 4, c4 = idx & 15;
                rgK[l] = *(const float4*)(Kg + (size_t)(jn * 64 + row) * E_ + c4 * 4);
            }
            flash_issue_v(sb + ((jn & 1) * FSTG), Vtg, jn, tid);
        }

        // ---- S = Q K^T (bf16 2-split: 3 MMAs per k16 slice) ----
        float sc[8][4] = {};
        #pragma unroll
        for (int s = 0; s < 4; s++) {
            uint32_t kh[4][4], kl[4][4];
            #pragma unroll
            for (int p = 0; p < 4; p++) {
                const uint32_t ad = cur + bK[p] + s * 32;
                ldsm4(kh[p][0], kh[p][1], kh[p][2], kh[p][3], sb + ad);
                ldsm4(kl[p][0], kl[p][1], kl[p][2], kl[p][3], sb + KHALF + ad);
            }
            #pragma unroll
            for (int nt = 0; nt < 8; nt++) {
                const uint32_t b0h = kh[nt >> 1][(nt & 1) * 2];
                const uint32_t b1h = kh[nt >> 1][(nt & 1) * 2 + 1];
                const uint32_t b0l = kl[nt >> 1][(nt & 1) * 2];
                const uint32_t b1l = kl[nt >> 1][(nt & 1) * 2 + 1];
                mma_bf16(sc[nt], qh[s], b0h, b1h);
                mma_bf16(sc[nt], qh[s], b0l, b1l);
                mma_bf16(sc[nt], ql[s], b0h, b1h);
            }
        }

        // ---- softmax (registers + quad shuffles) ----
        const bool maskt = (jt >= 2 * qt);
        const int qr1 = qt * 128 + wq + (lane >> 2);
        const int kcb = jt * 64 + 2 * (lane & 3);
        #pragma unroll
        for (int ri = 0; ri < 2; ri++) {
            const int qrow = qr1 + ri * 8;
            float mx = NEGINF;
            #pragma unroll
            for (int nt = 0; nt < 8; nt++) {
                float s0 = sc[nt][2 * ri] * 8.0f;
                float s1 = sc[nt][2 * ri + 1] * 8.0f;
                if (maskt) {
                    const int c = kcb + nt * 8;
                    if (c > qrow)     s0 = NEGINF;
                    if (c + 1 > qrow) s1 = NEGINF;
                }
                sc[nt][2 * ri]     = s0;
                sc[nt][2 * ri + 1] = s1;
                mx = fmaxf(mx, fmaxf(s0, s1));
            }
            mx = fmaxf(mx, __shfl_xor_sync(0xffffffffu, mx, 1));
            mx = fmaxf(mx, __shfl_xor_sync(0xffffffffu, mx, 2));
            const float mnew = fmaxf(mrow[ri], mx);
            const float alpha = __expf(mrow[ri] - mnew);
            float sum = 0.0f;
            #pragma unroll
            for (int nt = 0; nt < 8; nt++) {
                const float p0 = __expf(sc[nt][2 * ri] - mnew);
                const float p1 = __expf(sc[nt][2 * ri + 1] - mnew);
                sc[nt][2 * ri] = p0; sc[nt][2 * ri + 1] = p1;
                sum += p0 + p1;
                o[nt][2 * ri]     *= alpha;
                o[nt][2 * ri + 1] *= alpha;
            }
            sum += __shfl_xor_sync(0xffffffffu, sum, 1);
            sum += __shfl_xor_sync(0xffffffffu, sum, 2);
            lrow[ri] = lrow[ri] * alpha + sum;
            mrow[ri] = mnew;
        }

        // ---- O += P V: P relayout via quad shuffles, single tf32 stream ----
        #pragma unroll
        for (int kk = 0; kk < 8; kk++) {
            float v00 = __shfl_sync(0xffffffffu, sc[kk][0], srcA);
            float v01 = __shfl_sync(0xffffffffu, sc[kk][1], srcA);
            float v10 = __shfl_sync(0xffffffffu, sc[kk][0], srcB);
            float v11 = __shfl_sync(0xffffffffu, sc[kk][1], srcB);
            float w00 = __shfl_sync(0xffffffffu, sc[kk][2], srcA);
            float w01 = __shfl_sync(0xffffffffu, sc[kk][3], srcA);
            float w10 = __shfl_sync(0xffffffffu, sc[kk][2], srcB);
            float w11 = __shfl_sync(0xffffffffu, sc[kk][3], srcB);
            uint32_t ph[4];
            ph[0] = tf32_bits(selo ? v01 : v00);
            ph[1] = tf32_bits(selo ? w01 : w00);
            ph[2] = tf32_bits(selo ? v11 : v10);
            ph[3] = tf32_bits(selo ? w11 : w10);

            const uint32_t cof = cur + VOF + (kk >> 2) * 8192;
            const uint32_t colb = (kk & 3) * 32;
            uint32_t vh[4][4];
            #pragma unroll
            for (int p = 0; p < 4; p++) {
                uint32_t vr[4];
                ldsm4(vr[0], vr[1], vr[2], vr[3], sb + cof + bR[p] + (colb ^ bX));
                cvt4(vr, vh[p]);
            }
            #pragma unroll
            for (int nt = 0; nt < 8; nt++)
                mma_tf32(o[nt], ph, vh[nt >> 1][(nt & 1) * 2],
                                    vh[nt >> 1][(nt & 1) * 2 + 1]);
        }
    }

    // ---- normalize + write ----
    const float inv0 = 1.0f / lrow[0];
    const float inv1 = 1.0f / lrow[1];
    const int gr1 = qt * 128 + wq + (lane >> 2);
    #pragma unroll
    for (int nt = 0; nt < 8; nt++) {
        const int col = nt * 8 + 2 * (lane & 3);
        *(float2*)(Og + (size_t)gr1 * E_ + col) =
            make_float2(o[nt][0] * inv0, o[nt][1] * inv0);
        *(float2*)(Og + (size_t)(gr1 + 8) * E_ + col) =
            make_float2(o[nt][2] * inv1, o[nt][3] * inv1);
    }
}

// ===========================================================================
extern "C" void kernel_launch(void* const* d_in, const int* in_sizes, int n_in,
                              void* d_out, int out_size)
{
    const float* x  = (const float*)d_in[0];
    const float* Wq = (const float*)d_in[1];
    const float* Wk = (const float*)d_in[2];
    const float* Wv = (const float*)d_in[3];
    const float* Wo = (const float*)d_in[4];
    float* out = (float*)d_out;

    cudaFuncSetAttribute(tc_gemm_qkv, cudaFuncAttributeMaxDynamicSharedMemorySize, GEMM_SMEM);
    cudaFuncSetAttribute(tc_gemm_o,   cudaFuncAttributeMaxDynamicSharedMemorySize, GEMM_SMEM);
    cudaFuncSetAttribute(flash_mma,   cudaFuncAttributeMaxDynamicSharedMemorySize, FST_TOTAL);

    dim3 gq(24, 32);
    tc_gemm_qkv<<<gq, 256, GEMM_SMEM>>>(x, Wq, Wk, Wv);

    dim3 gt(32, 16, 2);
    v_transpose<<<gt, 256>>>();

    dim3 ga(S_ / 128, H_, B_);
    flash_mma<<<ga, 256, FST_TOTAL>>>();

    dim3 go(8, 32);
    tc_gemm_o<<<go, 256, GEMM_SMEM>>>(Wo, out);
}